// round 1
// baseline (speedup 1.0000x reference)
#include <cuda_runtime.h>

#define NROWS 8192
#define NDIM  512
#define NTOP  100
#define NPART 64

__device__ double g_rinv[NROWS];
__device__ double g_spart[NPART][NDIM];
__device__ double g_s[NDIM];
__device__ unsigned long long g_key[NROWS];

// ---------------------------------------------------------------------------
// K1: one warp per row -> rinv[i] = 1/||x_i||  (fp64 accumulation)
// ---------------------------------------------------------------------------
__global__ void k_rinv(const float* __restrict__ x) {
    int warp = (blockIdx.x * blockDim.x + threadIdx.x) >> 5;
    int lane = threadIdx.x & 31;
    const float* xr = x + (size_t)warp * NDIM;
    double acc = 0.0;
    #pragma unroll
    for (int k = 0; k < NDIM / 32; ++k) {
        double v = (double)xr[lane + 32 * k];
        acc = fma(v, v, acc);
    }
    #pragma unroll
    for (int o = 16; o; o >>= 1) acc += __shfl_down_sync(0xffffffffu, acc, o);
    if (lane == 0) g_rinv[warp] = 1.0 / sqrt(acc);
}

// ---------------------------------------------------------------------------
// K2: column sums of unit vectors. 64 blocks x 256 thr (8 warps).
// Each warp owns 16 rows; lane owns dims lane+32k (k=0..15) in registers.
// Block-level reduce into g_spart[block][dim]. Fully deterministic.
// ---------------------------------------------------------------------------
__global__ void k_colsum(const float* __restrict__ x) {
    __shared__ double sblk[8][NDIM];
    int wid  = threadIdx.x >> 5;
    int lane = threadIdx.x & 31;
    int gw   = blockIdx.x * 8 + wid;   // 512 warps total

    double acc[16];
    #pragma unroll
    for (int k = 0; k < 16; ++k) acc[k] = 0.0;

    for (int r = 0; r < 16; ++r) {
        int row = gw * 16 + r;
        double rinv = g_rinv[row];
        const float* xr = x + (size_t)row * NDIM;
        #pragma unroll
        for (int k = 0; k < 16; ++k)
            acc[k] = fma((double)xr[lane + 32 * k], rinv, acc[k]);
    }
    #pragma unroll
    for (int k = 0; k < 16; ++k) sblk[wid][lane + 32 * k] = acc[k];
    __syncthreads();

    for (int d = threadIdx.x; d < NDIM; d += 256) {
        double s = 0.0;
        #pragma unroll
        for (int w = 0; w < 8; ++w) s += sblk[w][d];
        g_spart[blockIdx.x][d] = s;
    }
}

// K2b: reduce 64 partials -> g_s (1 block, 512 threads, coalesced)
__global__ void k_colsum_final() {
    int d = threadIdx.x;
    double s = 0.0;
    #pragma unroll 8
    for (int p = 0; p < NPART; ++p) s += g_spart[p][d];
    g_s[d] = s;
}

// ---------------------------------------------------------------------------
// K3: one warp per row: score_i = (x_i . s) * rinv_i (fp64).
// Emit order-preserving uint64 key with the row index in the low 13 bits
// (stable tie-break, unique keys).
// ---------------------------------------------------------------------------
__global__ void k_score(const float* __restrict__ x) {
    int warp = (blockIdx.x * blockDim.x + threadIdx.x) >> 5;
    int lane = threadIdx.x & 31;
    const float* xr = x + (size_t)warp * NDIM;
    double acc = 0.0;
    #pragma unroll
    for (int k = 0; k < 16; ++k) {
        int d = lane + 32 * k;
        acc = fma((double)xr[d], g_s[d], acc);
    }
    #pragma unroll
    for (int o = 16; o; o >>= 1) acc += __shfl_down_sync(0xffffffffu, acc, o);
    if (lane == 0) {
        double score = acc * g_rinv[warp];
        long long bits = __double_as_longlong(score);
        unsigned long long u = (unsigned long long)bits;
        u = (bits < 0) ? ~u : (u | 0x8000000000000000ULL);  // order-preserving map
        u = (u & ~0x1FFFULL) | (unsigned long long)warp;    // stable tie-break
        g_key[warp] = u;
    }
}

// ---------------------------------------------------------------------------
// K4: single-block selection. Keys in dynamic smem (64 KB).
// 1) binary search for exact 100th-smallest key
// 2) collect the exactly-100 candidates
// 3) cooperative rank-count per candidate -> rank2row
// 4) gather rows + write indices
// ---------------------------------------------------------------------------
extern "C" __global__ void k_select(const float* __restrict__ x,
                                    float* __restrict__ out, int out_size) {
    extern __shared__ unsigned long long s_keys[];
    __shared__ int warp_part[32];
    __shared__ int sh_total;
    __shared__ int cand[256];
    __shared__ int ncand;
    __shared__ int rank2row[NTOP];

    int t = threadIdx.x;  // 1024 threads
    for (int i = t; i < NROWS; i += 1024) s_keys[i] = g_key[i];
    if (t == 0) ncand = 0;
    __syncthreads();

    // --- binary search for K100 = 100th smallest key ---
    unsigned long long lo = 0ULL, hi = ~0ULL;
    for (int it = 0; it < 64; ++it) {
        unsigned long long mid = lo + ((hi - lo) >> 1);
        int c = 0;
        #pragma unroll
        for (int k = 0; k < 8; ++k) c += (s_keys[t + 1024 * k] <= mid) ? 1 : 0;
        #pragma unroll
        for (int o = 16; o; o >>= 1) c += __shfl_down_sync(0xffffffffu, c, o);
        if ((t & 31) == 0) warp_part[t >> 5] = c;
        __syncthreads();
        if (t < 32) {
            int v = warp_part[t];
            #pragma unroll
            for (int o = 16; o; o >>= 1) v += __shfl_down_sync(0xffffffffu, v, o);
            if (t == 0) sh_total = v;
        }
        __syncthreads();
        if (sh_total >= NTOP) hi = mid; else lo = mid + 1ULL;
    }
    unsigned long long kth = hi;

    // --- collect candidates (exactly NTOP since keys are unique) ---
    #pragma unroll
    for (int k = 0; k < 8; ++k) {
        int i = t + 1024 * k;
        if (s_keys[i] <= kth) {
            int p = atomicAdd(&ncand, 1);
            if (p < 256) cand[p] = i;
        }
    }
    __syncthreads();
    int nc = ncand;
    if (nc > NTOP) nc = NTOP + 0;  // safety (cannot happen: keys unique)

    // --- exact rank per candidate ---
    for (int c = 0; c < nc; ++c) {
        unsigned long long ck = s_keys[cand[c]];
        int cnt = 0;
        #pragma unroll
        for (int k = 0; k < 8; ++k) cnt += (s_keys[t + 1024 * k] < ck) ? 1 : 0;
        #pragma unroll
        for (int o = 16; o; o >>= 1) cnt += __shfl_down_sync(0xffffffffu, cnt, o);
        if ((t & 31) == 0) warp_part[t >> 5] = cnt;
        __syncthreads();
        if (t < 32) {
            int v = warp_part[t];
            #pragma unroll
            for (int o = 16; o; o >>= 1) v += __shfl_down_sync(0xffffffffu, v, o);
            if (t == 0 && v < NTOP) rank2row[v] = cand[c];
        }
        __syncthreads();
    }

    // --- output: 100 rows of 512 floats, then 100 indices (as float) ---
    const int nvec = NTOP * NDIM;  // 51200
    for (int e = t; e < nvec; e += 1024) {
        if (e >= out_size) break;
        int r = e >> 9, d = e & (NDIM - 1);
        out[e] = x[(size_t)rank2row[r] * NDIM + d];
    }
    if (t < NTOP && (nvec + t) < out_size)
        out[nvec + t] = (float)rank2row[t];
}

// ---------------------------------------------------------------------------
extern "C" void kernel_launch(void* const* d_in, const int* in_sizes, int n_in,
                              void* d_out, int out_size) {
    const float* x = (const float*)d_in[0];
    float* out = (float*)d_out;

    static bool attr_set = false;
    if (!attr_set) {
        cudaFuncSetAttribute(k_select, cudaFuncAttributeMaxDynamicSharedMemorySize,
                             NROWS * (int)sizeof(unsigned long long));
        attr_set = true;
    }

    k_rinv<<<1024, 256>>>(x);          // 8192 warps, 1 row each
    k_colsum<<<64, 256>>>(x);          // 512 warps, 16 rows each
    k_colsum_final<<<1, 512>>>();
    k_score<<<1024, 256>>>(x);         // 8192 warps, 1 row each
    k_select<<<1, 1024, NROWS * sizeof(unsigned long long)>>>(x, out, out_size);
}

// round 2
// speedup vs baseline: 4.7537x; 4.7537x over previous
#include <cuda_runtime.h>

#define NROWS 8192
#define NDIM  512
#define ND4   128      // NDIM/4
#define NTOP  100
#define NBLKA 128      // colsum blocks

__device__ float  g_rinv[NROWS];
__device__ float4 g_spart[NBLKA][ND4];
__device__ float4 g_s4[ND4];
__device__ unsigned int g_key[NROWS];
__device__ int    g_rank2row[NTOP];

// ---------------------------------------------------------------------------
// KA: fused per-row 1/||x|| + column-sum of unit rows. 128 blocks x 256 thr.
// Warp handles 8 rows; lane owns dims (lane+32k)*4+c in float4 registers.
// Deterministic fixed-order reduction.
// ---------------------------------------------------------------------------
__global__ void kA(const float4* __restrict__ x4) {
    __shared__ float4 sacc[8][ND4];   // 16 KB
    int wid  = threadIdx.x >> 5;
    int lane = threadIdx.x & 31;
    int gw   = blockIdx.x * 8 + wid;  // 0..1023, 8 rows each

    float4 acc[4];
    #pragma unroll
    for (int k = 0; k < 4; ++k) acc[k] = make_float4(0.f, 0.f, 0.f, 0.f);

    #pragma unroll
    for (int r = 0; r < 8; ++r) {
        int row = gw * 8 + r;
        const float4* xr = x4 + (size_t)row * ND4;
        float4 v[4];
        #pragma unroll
        for (int k = 0; k < 4; ++k) v[k] = xr[lane + 32 * k];

        float sq = 0.f;
        #pragma unroll
        for (int k = 0; k < 4; ++k)
            sq += v[k].x*v[k].x + v[k].y*v[k].y + v[k].z*v[k].z + v[k].w*v[k].w;
        #pragma unroll
        for (int o = 16; o; o >>= 1) sq += __shfl_xor_sync(0xffffffffu, sq, o);

        float rinv = (float)(1.0 / sqrt((double)sq));
        if (lane == 0) g_rinv[row] = rinv;

        #pragma unroll
        for (int k = 0; k < 4; ++k) {
            acc[k].x = fmaf(v[k].x, rinv, acc[k].x);
            acc[k].y = fmaf(v[k].y, rinv, acc[k].y);
            acc[k].z = fmaf(v[k].z, rinv, acc[k].z);
            acc[k].w = fmaf(v[k].w, rinv, acc[k].w);
        }
    }
    #pragma unroll
    for (int k = 0; k < 4; ++k) sacc[wid][lane + 32 * k] = acc[k];
    __syncthreads();

    if (threadIdx.x < ND4) {
        int d = threadIdx.x;
        float4 s = sacc[0][d];
        #pragma unroll
        for (int w = 1; w < 8; ++w) {
            float4 t = sacc[w][d];
            s.x += t.x; s.y += t.y; s.z += t.z; s.w += t.w;
        }
        g_spart[blockIdx.x][d] = s;
    }
}

// ---------------------------------------------------------------------------
// KB: reduce 128 partials -> g_s4. 1 block x 512 threads, 2-level.
// ---------------------------------------------------------------------------
__global__ void kB() {
    __shared__ float4 part[4][ND4];
    int d = threadIdx.x & (ND4 - 1);
    int q = threadIdx.x >> 7;         // 0..3, each sums 32 partials
    float4 s = make_float4(0.f, 0.f, 0.f, 0.f);
    #pragma unroll 4
    for (int p = q * 32; p < (q + 1) * 32; ++p) {
        float4 t = g_spart[p][d];
        s.x += t.x; s.y += t.y; s.z += t.z; s.w += t.w;
    }
    part[q][d] = s;
    __syncthreads();
    if (threadIdx.x < ND4) {
        float4 a = part[0][d], b = part[1][d], c = part[2][d], e = part[3][d];
        a.x += b.x + c.x + e.x; a.y += b.y + c.y + e.y;
        a.z += b.z + c.z + e.z; a.w += b.w + c.w + e.w;
        g_s4[d] = a;
    }
}

// ---------------------------------------------------------------------------
// KC: one warp per row: score = (x_i . s) * rinv_i (fp32, unscaled — monotone).
// Emit order-preserving uint32 key.
// ---------------------------------------------------------------------------
__global__ void kC(const float4* __restrict__ x4) {
    int warp = (blockIdx.x * blockDim.x + threadIdx.x) >> 5;
    int lane = threadIdx.x & 31;
    const float4* xr = x4 + (size_t)warp * ND4;
    float dot = 0.f;
    #pragma unroll
    for (int k = 0; k < 4; ++k) {
        float4 v = xr[lane + 32 * k];
        float4 s = g_s4[lane + 32 * k];
        dot = fmaf(v.x, s.x, dot);
        dot = fmaf(v.y, s.y, dot);
        dot = fmaf(v.z, s.z, dot);
        dot = fmaf(v.w, s.w, dot);
    }
    #pragma unroll
    for (int o = 16; o; o >>= 1) dot += __shfl_down_sync(0xffffffffu, dot, o);
    if (lane == 0) {
        float score = dot * g_rinv[warp];
        unsigned int u = __float_as_uint(score);
        u = (u & 0x80000000u) ? ~u : (u | 0x80000000u);  // order-preserving
        g_key[warp] = u;
    }
}

// ---------------------------------------------------------------------------
// KD: single-block selection. Keys live in REGISTERS (8/thread).
// 32-iter binary search for kth32, candidate collect (ties handled),
// rank among <=256 candidates with (key, index) tie-break.
// ---------------------------------------------------------------------------
extern "C" __global__ void kD(float* __restrict__ out, int out_size) {
    __shared__ int warp_part[32];
    __shared__ int stot;
    __shared__ unsigned int ckey[256];
    __shared__ int cidx[256];
    __shared__ int ncand;

    int t = threadIdx.x;  // 1024 threads
    unsigned int k[8];
    #pragma unroll
    for (int j = 0; j < 8; ++j) k[j] = g_key[t + 1024 * j];
    if (t == 0) ncand = 0;

    unsigned int lo = 0u, hi = 0xFFFFFFFFu;
    for (int it = 0; it < 32; ++it) {
        unsigned int mid = lo + ((hi - lo) >> 1);
        int c = 0;
        #pragma unroll
        for (int j = 0; j < 8; ++j) c += (k[j] <= mid) ? 1 : 0;
        #pragma unroll
        for (int o = 16; o; o >>= 1) c += __shfl_down_sync(0xffffffffu, c, o);
        if ((t & 31) == 0) warp_part[t >> 5] = c;
        __syncthreads();
        if (t < 32) {
            int v = warp_part[t];
            #pragma unroll
            for (int o = 16; o; o >>= 1) v += __shfl_down_sync(0xffffffffu, v, o);
            if (t == 0) stot = v;
        }
        __syncthreads();
        if (stot >= NTOP) hi = mid; else lo = mid + 1u;
    }
    unsigned int kth = hi;

    // collect candidates (all keys <= kth; >=100, small overshoot only on ties)
    #pragma unroll
    for (int j = 0; j < 8; ++j) {
        if (k[j] <= kth) {
            int p = atomicAdd(&ncand, 1);
            if (p < 256) { ckey[p] = k[j]; cidx[p] = t + 1024 * j; }
        }
    }
    __syncthreads();
    int nc = ncand < 256 ? ncand : 256;

    // exact rank among candidates (stable: index ascending on ties)
    if (t < nc) {
        unsigned int mk = ckey[t];
        int mi = cidx[t];
        int rank = 0;
        for (int j = 0; j < nc; ++j)
            rank += (ckey[j] < mk || (ckey[j] == mk && cidx[j] < mi)) ? 1 : 0;
        if (rank < NTOP) {
            g_rank2row[rank] = mi;
            if (NTOP * NDIM + rank < out_size)
                out[NTOP * NDIM + rank] = (float)mi;
        }
    }
}

// ---------------------------------------------------------------------------
// KE: parallel gather of the 100 selected rows (one block per row, float4).
// ---------------------------------------------------------------------------
__global__ void kE(const float4* __restrict__ x4, float4* __restrict__ out4,
                   int out_size) {
    int r = blockIdx.x;
    int row = g_rank2row[r];
    int e = r * ND4 + threadIdx.x;         // float4 index
    if (4 * e + 4 <= out_size)
        out4[e] = x4[(size_t)row * ND4 + threadIdx.x];
}

// ---------------------------------------------------------------------------
extern "C" void kernel_launch(void* const* d_in, const int* in_sizes, int n_in,
                              void* d_out, int out_size) {
    const float4* x4 = (const float4*)d_in[0];
    float* out = (float*)d_out;

    kA<<<NBLKA, 256>>>(x4);
    kB<<<1, 512>>>();
    kC<<<1024, 256>>>(x4);
    kD<<<1, 1024>>>(out, out_size);
    kE<<<NTOP, ND4>>>(x4, (float4*)d_out, out_size);
}

// round 3
// speedup vs baseline: 6.2163x; 1.3077x over previous
#include <cuda_runtime.h>

#define NROWS 8192
#define NDIM  512
#define ND4   128      // NDIM/4
#define NTOP  100
#define NBLKA 128

__device__ float  g_rinv[NROWS];
__device__ float4 g_spart[NBLKA][ND4];
__device__ float4 g_s4[ND4];
__device__ unsigned int g_key[NROWS];
__device__ int    g_rank2row[NTOP];
__device__ unsigned int g_ctr = 0;

// ---------------------------------------------------------------------------
// KA: fused per-row 1/||x|| + column-sum of unit rows + last-block final
// reduction into g_s4. 128 blocks x 256 thr. Deterministic fixed-order sums.
// ---------------------------------------------------------------------------
__global__ void kA(const float4* __restrict__ x4) {
    __shared__ float4 sacc[8][ND4];   // 16 KB
    __shared__ float4 sred[2][ND4];   // final-reduce scratch (4 KB)
    __shared__ int    s_last;
    int wid  = threadIdx.x >> 5;
    int lane = threadIdx.x & 31;
    int gw   = blockIdx.x * 8 + wid;  // 0..1023, 8 rows each

    float4 acc[4];
    #pragma unroll
    for (int k = 0; k < 4; ++k) acc[k] = make_float4(0.f, 0.f, 0.f, 0.f);

    #pragma unroll
    for (int r = 0; r < 8; ++r) {
        int row = gw * 8 + r;
        const float4* xr = x4 + (size_t)row * ND4;
        float4 v[4];
        #pragma unroll
        for (int k = 0; k < 4; ++k) v[k] = xr[lane + 32 * k];

        float sq = 0.f;
        #pragma unroll
        for (int k = 0; k < 4; ++k)
            sq += v[k].x*v[k].x + v[k].y*v[k].y + v[k].z*v[k].z + v[k].w*v[k].w;
        #pragma unroll
        for (int o = 16; o; o >>= 1) sq += __shfl_xor_sync(0xffffffffu, sq, o);

        float rinv = rsqrtf(sq);
        rinv = rinv * (1.5f - 0.5f * sq * rinv * rinv);  // Newton refine
        if (lane == 0) g_rinv[row] = rinv;

        #pragma unroll
        for (int k = 0; k < 4; ++k) {
            acc[k].x = fmaf(v[k].x, rinv, acc[k].x);
            acc[k].y = fmaf(v[k].y, rinv, acc[k].y);
            acc[k].z = fmaf(v[k].z, rinv, acc[k].z);
            acc[k].w = fmaf(v[k].w, rinv, acc[k].w);
        }
    }
    #pragma unroll
    for (int k = 0; k < 4; ++k) sacc[wid][lane + 32 * k] = acc[k];
    __syncthreads();

    if (threadIdx.x < ND4) {
        int d = threadIdx.x;
        float4 s = sacc[0][d];
        #pragma unroll
        for (int w = 1; w < 8; ++w) {
            float4 t = sacc[w][d];
            s.x += t.x; s.y += t.y; s.z += t.z; s.w += t.w;
        }
        g_spart[blockIdx.x][d] = s;
    }
    __threadfence();
    __syncthreads();
    if (threadIdx.x == 0)
        s_last = (atomicAdd(&g_ctr, 1u) == NBLKA - 1) ? 1 : 0;
    __syncthreads();

    if (s_last) {
        __threadfence();  // acquire partials
        int d = threadIdx.x & (ND4 - 1);
        int q = threadIdx.x >> 7;         // 0 or 1, each sums 64 partials
        float4 s = make_float4(0.f, 0.f, 0.f, 0.f);
        #pragma unroll 4
        for (int p = q * 64; p < (q + 1) * 64; ++p) {
            float4 t = g_spart[p][d];
            s.x += t.x; s.y += t.y; s.z += t.z; s.w += t.w;
        }
        sred[q][d] = s;
        __syncthreads();
        if (threadIdx.x < ND4) {
            float4 a = sred[0][d], b = sred[1][d];
            a.x += b.x; a.y += b.y; a.z += b.z; a.w += b.w;
            g_s4[d] = a;
        }
        if (threadIdx.x == 0) g_ctr = 0;  // reset for next graph replay
    }
}

// ---------------------------------------------------------------------------
// KC: one warp per row: score = (x_i . s) * rinv_i; order-preserving u32 key.
// ---------------------------------------------------------------------------
__global__ void kC(const float4* __restrict__ x4) {
    int warp = (blockIdx.x * blockDim.x + threadIdx.x) >> 5;
    int lane = threadIdx.x & 31;
    const float4* xr = x4 + (size_t)warp * ND4;
    float dot = 0.f;
    #pragma unroll
    for (int k = 0; k < 4; ++k) {
        float4 v = xr[lane + 32 * k];
        float4 s = g_s4[lane + 32 * k];
        dot = fmaf(v.x, s.x, dot);
        dot = fmaf(v.y, s.y, dot);
        dot = fmaf(v.z, s.z, dot);
        dot = fmaf(v.w, s.w, dot);
    }
    #pragma unroll
    for (int o = 16; o; o >>= 1) dot += __shfl_down_sync(0xffffffffu, dot, o);
    if (lane == 0) {
        float score = dot * g_rinv[warp];
        unsigned int u = __float_as_uint(score);
        u = (u & 0x80000000u) ? ~u : (u | 0x80000000u);
        g_key[warp] = u;
    }
}

// ---------------------------------------------------------------------------
// KD: single-block MSB-first radix select (4 x 8-bit rounds), then exact
// rank among <=256 candidates with (key, index) stable tie-break.
// ---------------------------------------------------------------------------
extern "C" __global__ void kD(float* __restrict__ out, int out_size) {
    __shared__ int hist[256];
    __shared__ unsigned int sh_prefix;
    __shared__ int sh_needed;
    __shared__ unsigned int ckey[256];
    __shared__ int cidx[256];
    __shared__ int ncand;

    int t = threadIdx.x;  // 1024 threads
    int lane = t & 31;
    unsigned int k[8];
    #pragma unroll
    for (int j = 0; j < 8; ++j) k[j] = g_key[t + 1024 * j];
    if (t == 0) ncand = 0;

    unsigned int prefix = 0;
    int needed = NTOP;

    #pragma unroll
    for (int round = 0; round < 4; ++round) {
        const int shift = 24 - 8 * round;
        if (t < 256) hist[t] = 0;
        __syncthreads();

        #pragma unroll
        for (int j = 0; j < 8; ++j) {
            bool ok;
            if (round == 0) ok = true;
            else            ok = ((k[j] >> (shift + 8)) == prefix);
            unsigned int active = __ballot_sync(0xffffffffu, ok);
            if (ok) {
                int bin = (k[j] >> shift) & 0xFF;
                unsigned int same = __match_any_sync(active, bin);
                int leader = __ffs(same) - 1;
                if (lane == leader) atomicAdd(&hist[bin], __popc(same));
            }
        }
        __syncthreads();

        if (t < 32) {
            int local[8]; int lsum = 0;
            #pragma unroll
            for (int i = 0; i < 8; ++i) { local[i] = hist[t * 8 + i]; lsum += local[i]; }
            int v = lsum;
            #pragma unroll
            for (int o = 1; o < 32; o <<= 1) {
                int u = __shfl_up_sync(0xffffffffu, v, o);
                if (lane >= o) v += u;
            }
            int run = v - lsum;  // exclusive prefix across lanes
            #pragma unroll
            for (int i = 0; i < 8; ++i) {
                if (run < needed && needed <= run + local[i]) {
                    sh_prefix = (prefix << 8) | (unsigned int)(t * 8 + i);
                    sh_needed = needed - run;
                }
                run += local[i];
            }
        }
        __syncthreads();
        prefix = sh_prefix;
        needed = sh_needed;
        __syncthreads();
    }
    unsigned int kth = prefix;  // exact value of the 100th-smallest key

    // collect candidates (keys <= kth; >=100, overshoot only on exact ties)
    #pragma unroll
    for (int j = 0; j < 8; ++j) {
        if (k[j] <= kth) {
            int p = atomicAdd(&ncand, 1);
            if (p < 256) { ckey[p] = k[j]; cidx[p] = t + 1024 * j; }
        }
    }
    __syncthreads();
    int nc = ncand < 256 ? ncand : 256;

    // exact rank among candidates (stable: index ascending on key ties)
    if (t < nc) {
        unsigned int mk = ckey[t];
        int mi = cidx[t];
        int rank = 0;
        for (int j = 0; j < nc; ++j)
            rank += (ckey[j] < mk || (ckey[j] == mk && cidx[j] < mi)) ? 1 : 0;
        if (rank < NTOP) {
            g_rank2row[rank] = mi;
            if (NTOP * NDIM + rank < out_size)
                out[NTOP * NDIM + rank] = (float)mi;
        }
    }
}

// ---------------------------------------------------------------------------
// KE: parallel gather of the 100 selected rows (one block per row, float4).
// ---------------------------------------------------------------------------
__global__ void kE(const float4* __restrict__ x4, float4* __restrict__ out4,
                   int out_size) {
    int r = blockIdx.x;
    int row = g_rank2row[r];
    int e = r * ND4 + threadIdx.x;
    if (4 * e + 4 <= out_size)
        out4[e] = x4[(size_t)row * ND4 + threadIdx.x];
}

// ---------------------------------------------------------------------------
extern "C" void kernel_launch(void* const* d_in, const int* in_sizes, int n_in,
                              void* d_out, int out_size) {
    const float4* x4 = (const float4*)d_in[0];
    float* out = (float*)d_out;

    kA<<<NBLKA, 256>>>(x4);
    kC<<<1024, 256>>>(x4);
    kD<<<1, 1024>>>(out, out_size);
    kE<<<NTOP, ND4>>>(x4, (float4*)d_out, out_size);
}